// round 1
// baseline (speedup 1.0000x reference)
#include <cuda_runtime.h>
#include <math.h>

#define NB 32
#define NQ 900
#define NT 300
#define NC 256

#define W_CLASS 1.0f
#define W_BBOX  5.0f
#define W_GIOU  2.0f
#define W_CUTIN 2.0f

// Scratch (allocation-free rule: __device__ globals)
__device__ float g_CT[(size_t)NB * NT * NQ];   // transposed cost: [b][t][q]
__device__ float g_rmax[NB * NQ];
__device__ float g_rsum[NB * NQ];

// ---------------------------------------------------------------------------
// Kernel 1: per-(b,q) softmax stats (max, sum of exp) over C=256. 1 warp/row.
// ---------------------------------------------------------------------------
__global__ void softmax_stats_kernel(const float* __restrict__ logits) {
    int warp = (blockIdx.x * blockDim.x + threadIdx.x) >> 5;
    int lane = threadIdx.x & 31;
    if (warp >= NB * NQ) return;
    const float* row = logits + (size_t)warp * NC;
    float vals[NC / 32];
    float m = -INFINITY;
#pragma unroll
    for (int k = 0; k < NC / 32; k++) {
        vals[k] = row[lane + 32 * k];
        m = fmaxf(m, vals[k]);
    }
#pragma unroll
    for (int o = 16; o; o >>= 1) m = fmaxf(m, __shfl_xor_sync(0xffffffffu, m, o));
    float s = 0.f;
#pragma unroll
    for (int k = 0; k < NC / 32; k++) s += expf(vals[k] - m);
#pragma unroll
    for (int o = 16; o; o >>= 1) s += __shfl_xor_sync(0xffffffffu, s, o);
    if (lane == 0) { g_rmax[warp] = m; g_rsum[warp] = s; }
}

// ---------------------------------------------------------------------------
// Kernel 2: cost matrix C[b][q][t].  One block per (q,b), threads over t.
// ---------------------------------------------------------------------------
__global__ void cost_kernel(const float* __restrict__ logits,
                            const float* __restrict__ pboxes,
                            const float* __restrict__ pcut,
                            const int*   __restrict__ tlab,
                            const float* __restrict__ tboxes,
                            const float* __restrict__ tcut,
                            float* __restrict__ out) {
    int q = blockIdx.x, b = blockIdx.y;
    __shared__ float s_pb[4];
    __shared__ float s_pc, s_rm, s_rs;
    int tid = threadIdx.x;
    if (tid < 4)       s_pb[tid] = pboxes[(((size_t)b * NQ + q) << 2) + tid];
    else if (tid == 4) s_pc = pcut[b * NQ + q];
    else if (tid == 5) s_rm = g_rmax[b * NQ + q];
    else if (tid == 6) s_rs = g_rsum[b * NQ + q];
    __syncthreads();
    int t = tid;
    if (t >= NT) return;

    float px0 = s_pb[0], py0 = s_pb[1], px1 = s_pb[2], py1 = s_pb[3];
    const float* tb = tboxes + (((size_t)b * NT + t) << 2);
    float tx0 = tb[0], ty0 = tb[1], tx1 = tb[2], ty1 = tb[3];

    int lab = tlab[b * NT + t];
    float logit = logits[((size_t)b * NQ + q) * NC + lab];
    float prob = expf(logit - s_rm) / s_rs;
    float cost_class = -prob;

    float cost_bbox = fabsf(px0 - tx0) + fabsf(py0 - ty0) +
                      fabsf(px1 - tx1) + fabsf(py1 - ty1);

    float area_p = (px1 - px0) * (py1 - py0);
    float area_t = (tx1 - tx0) * (ty1 - ty0);
    float iw = fminf(px1, tx1) - fmaxf(px0, tx0);
    float ih = fminf(py1, ty1) - fmaxf(py0, ty0);
    float inter = fmaxf(iw, 0.f) * fmaxf(ih, 0.f);
    float uni = area_p + area_t - inter;
    float iou = inter / uni;
    float ew = fmaxf(px1, tx1) - fminf(px0, tx0);
    float eh = fmaxf(py1, ty1) - fminf(py0, ty0);
    float enc = fmaxf(ew, 0.f) * fmaxf(eh, 0.f);
    float giou = iou - (enc - uni) / enc;

    float ccut = fabsf(s_pc - tcut[b * NT + t]);

    float cost = W_BBOX * cost_bbox + W_CLASS * cost_class
               - W_GIOU * giou + W_CUTIN * ccut;
    out[((size_t)b * NQ + q) * NT + t] = cost;
}

// ---------------------------------------------------------------------------
// Kernel 3: transpose C[b][q][t] -> g_CT[b][t][q] (coalesced both sides)
// ---------------------------------------------------------------------------
__global__ void transpose_kernel(const float* __restrict__ in) {
    __shared__ float tile[32][33];
    int b = blockIdx.z;
    int t0 = blockIdx.x << 5, q0 = blockIdx.y << 5;
    int x = threadIdx.x, y = threadIdx.y;
#pragma unroll
    for (int r = 0; r < 32; r += 8) {
        int q = q0 + y + r, t = t0 + x;
        tile[y + r][x] = (q < NQ && t < NT) ? in[((size_t)b * NQ + q) * NT + t] : 0.f;
    }
    __syncthreads();
#pragma unroll
    for (int r = 0; r < 32; r += 8) {
        int t = t0 + y + r, q = q0 + x;
        if (t < NT && q < NQ) g_CT[((size_t)b * NT + t) * NQ + q] = tile[x][y + r];
    }
}

// ---------------------------------------------------------------------------
// Kernel 4: Jonker-Volgenant shortest augmenting path (exact replica of the
// reference's float64 arithmetic & np.argmin lowest-index tie-break).
// One CTA per batch; 1024 threads; column j handled by thread j-1.
// ---------------------------------------------------------------------------
__global__ void __launch_bounds__(1024)
lsa_kernel(float* __restrict__ outq, float* __restrict__ outt, int write_idx) {
    int b = blockIdx.x;
    int tid = threadIdx.x;

    __shared__ double u[NT + 1];
    __shared__ double v[NQ + 1];
    __shared__ double minv[NQ + 1];
    __shared__ int    p[NQ + 1];
    __shared__ int    way[NQ + 1];
    __shared__ unsigned char used[NQ + 1];
    __shared__ double s_wval[32];
    __shared__ int    s_widx[32];
    __shared__ int    s_j0, s_i0, s_j1;
    __shared__ double s_delta, s_ui0;

    for (int j = tid; j <= NQ; j += blockDim.x) { v[j] = 0.0; p[j] = 0; }
    for (int j = tid; j <= NT; j += blockDim.x) u[j] = 0.0;
    __syncthreads();

    const float* Cb = g_CT + (size_t)b * NT * NQ;

    for (int i = 1; i <= NT; i++) {
        if (tid <= NQ) { minv[tid] = 1e300; used[tid] = 0; }
        if (tid == 0) { p[0] = i; s_j0 = 0; }
        __syncthreads();

        while (true) {
            if (tid == 0) {
                int j0 = s_j0;
                used[j0] = 1;
                int i0 = p[j0];
                s_i0 = i0;
                s_ui0 = u[i0];
            }
            __syncthreads();
            int    i0cap = s_i0;
            int    j0cap = s_j0;
            double ui0   = s_ui0;
            const float* crow = Cb + (size_t)(i0cap - 1) * NQ;

            double bv = 1e300;
            int    bj = 0x7fffffff;
            if (tid < NQ) {
                int j = tid + 1;
                if (!used[j]) {
                    double cur = (double)crow[tid] - ui0 - v[j];
                    if (cur < minv[j]) { minv[j] = cur; way[j] = j0cap; }
                    bv = minv[j];
                    bj = j;
                }
            }
            // two-level argmin with lowest-index tie-break (matches np.argmin)
#pragma unroll
            for (int o = 16; o; o >>= 1) {
                double ov = __shfl_down_sync(0xffffffffu, bv, o);
                int    oj = __shfl_down_sync(0xffffffffu, bj, o);
                if (ov < bv || (ov == bv && oj < bj)) { bv = ov; bj = oj; }
            }
            if ((tid & 31) == 0) { s_wval[tid >> 5] = bv; s_widx[tid >> 5] = bj; }
            __syncthreads();
            if (tid < 32) {
                bv = s_wval[tid]; bj = s_widx[tid];
#pragma unroll
                for (int o = 16; o; o >>= 1) {
                    double ov = __shfl_down_sync(0xffffffffu, bv, o);
                    int    oj = __shfl_down_sync(0xffffffffu, bj, o);
                    if (ov < bv || (ov == bv && oj < bj)) { bv = ov; bj = oj; }
                }
                if (tid == 0) { s_delta = bv; s_j1 = bj; }
            }
            __syncthreads();
            double delta = s_delta;
            int    j1    = s_j1;
            if (tid <= NQ) {
                if (used[tid]) { u[p[tid]] += delta; v[tid] -= delta; }
                else if (tid >= 1) minv[tid] -= delta;
            }
            if (tid == 0) s_j0 = j1;
            __syncthreads();
            if (p[j1] == 0) break;
        }

        if (tid == 0) {
            int j0 = s_j0;
            while (j0) { int j1 = way[j0]; p[j0] = p[j1]; j0 = j1; }
        }
        __syncthreads();
    }

    if (write_idx) {
        if (tid >= 1 && tid <= NQ) {
            int r = p[tid];
            if (r > 0) outq[b * NT + (r - 1)] = (float)(tid - 1);
        }
        if (tid < NT) outt[b * NT + tid] = (float)tid;
    }
}

// ---------------------------------------------------------------------------
extern "C" void kernel_launch(void* const* d_in, const int* in_sizes, int n_in,
                              void* d_out, int out_size) {
    const float* logits = (const float*)d_in[0];
    const float* pboxes = (const float*)d_in[1];
    const float* pcut   = (const float*)d_in[2];
    const int*   tlab   = (const int*)d_in[3];
    const float* tboxes = (const float*)d_in[4];
    const float* tcut   = (const float*)d_in[5];
    float* out = (float*)d_out;

    int rows = NB * NQ;                       // softmax rows, 1 warp each
    int threads = 256;
    int blocks = (rows * 32 + threads - 1) / threads;
    softmax_stats_kernel<<<blocks, threads>>>(logits);

    dim3 cgrid(NQ, NB);
    cost_kernel<<<cgrid, 320>>>(logits, pboxes, pcut, tlab, tboxes, tcut, out);

    dim3 tgrid((NT + 31) / 32, (NQ + 31) / 32, NB);
    transpose_kernel<<<tgrid, dim3(32, 8)>>>(out);

    long long need = (long long)NB * NQ * NT + 2LL * NB * NT;
    int write_idx = (out_size >= need) ? 1 : 0;
    float* outq = out + (size_t)NB * NQ * NT;
    float* outt = outq + (size_t)NB * NT;
    lsa_kernel<<<NB, 1024>>>(outq, outt, write_idx);
}

// round 2
// speedup vs baseline: 1.1367x; 1.1367x over previous
#include <cuda_runtime.h>
#include <math.h>
#include <float.h>

#define NB 32
#define NQ 900
#define NT 300
#define NC 256

#define W_CLASS 1.0f
#define W_BBOX  5.0f
#define W_GIOU  2.0f
#define W_CUTIN 2.0f

// Scratch (allocation-free rule: __device__ globals)
__device__ float g_CT[(size_t)NB * NT * NQ];   // transposed cost: [b][t][q]
__device__ float g_rmax[NB * NQ];
__device__ float g_rsum[NB * NQ];

// ---------------------------------------------------------------------------
// Kernel 1: per-(b,q) softmax stats (max, sum of exp) over C=256. 1 warp/row.
// ---------------------------------------------------------------------------
__global__ void softmax_stats_kernel(const float* __restrict__ logits) {
    int warp = (blockIdx.x * blockDim.x + threadIdx.x) >> 5;
    int lane = threadIdx.x & 31;
    if (warp >= NB * NQ) return;
    const float* row = logits + (size_t)warp * NC;
    float vals[NC / 32];
    float m = -INFINITY;
#pragma unroll
    for (int k = 0; k < NC / 32; k++) {
        vals[k] = row[lane + 32 * k];
        m = fmaxf(m, vals[k]);
    }
#pragma unroll
    for (int o = 16; o; o >>= 1) m = fmaxf(m, __shfl_xor_sync(0xffffffffu, m, o));
    float s = 0.f;
#pragma unroll
    for (int k = 0; k < NC / 32; k++) s += expf(vals[k] - m);
#pragma unroll
    for (int o = 16; o; o >>= 1) s += __shfl_xor_sync(0xffffffffu, s, o);
    if (lane == 0) { g_rmax[warp] = m; g_rsum[warp] = s; }
}

// ---------------------------------------------------------------------------
// Kernel 2 (fused): cost matrix, written in BOTH layouts (out[b,q,t] and
// g_CT[b,t,q]) via a 32x32 smem tile. Saves the separate transpose pass.
// Block (32,8): x = t within tile, y strides over 4 q rows.
// ---------------------------------------------------------------------------
__global__ void __launch_bounds__(256)
cost_fused_kernel(const float* __restrict__ logits,
                  const float* __restrict__ pboxes,
                  const float* __restrict__ pcut,
                  const int*   __restrict__ tlab,
                  const float* __restrict__ tboxes,
                  const float* __restrict__ tcut,
                  float* __restrict__ out) {
    int b = blockIdx.z;
    int t0 = blockIdx.x << 5;
    int q0 = blockIdx.y << 5;

    __shared__ float s_tb[4][32];
    __shared__ int   s_lab[32];
    __shared__ float s_tc[32];
    __shared__ float s_pb[4][32];
    __shared__ float s_pc[32], s_rm[32], s_rs[32];
    __shared__ float tile[32][33];

    int tx = threadIdx.x, ty = threadIdx.y;
    int tid = ty * 32 + tx;

    if (tid < 32) {
        int t = t0 + tid;
        if (t < NT) {
            const float* tb = tboxes + (((size_t)b * NT + t) << 2);
            s_tb[0][tid] = tb[0]; s_tb[1][tid] = tb[1];
            s_tb[2][tid] = tb[2]; s_tb[3][tid] = tb[3];
            s_lab[tid] = tlab[b * NT + t];
            s_tc[tid]  = tcut[b * NT + t];
        }
    } else if (tid < 64) {
        int l = tid - 32; int q = q0 + l;
        if (q < NQ) {
            const float* pb = pboxes + (((size_t)b * NQ + q) << 2);
            s_pb[0][l] = pb[0]; s_pb[1][l] = pb[1];
            s_pb[2][l] = pb[2]; s_pb[3][l] = pb[3];
        }
    } else if (tid < 96) {
        int l = tid - 64; int q = q0 + l;
        if (q < NQ) {
            s_pc[l] = pcut[b * NQ + q];
            s_rm[l] = g_rmax[b * NQ + q];
            s_rs[l] = g_rsum[b * NQ + q];
        }
    }
    __syncthreads();

    int t = t0 + tx;
    bool tvalid = t < NT;
    float tbx0 = s_tb[0][tx], tby0 = s_tb[1][tx];
    float tbx1 = s_tb[2][tx], tby1 = s_tb[3][tx];
    int   lab  = tvalid ? s_lab[tx] : 0;
    float tcv  = s_tc[tx];
    float area_t = (tbx1 - tbx0) * (tby1 - tby0);

#pragma unroll
    for (int r = 0; r < 4; r++) {
        int ql = ty + 8 * r;
        int q  = q0 + ql;
        float cost = 0.f;
        if (tvalid && q < NQ) {
            float px0 = s_pb[0][ql], py0 = s_pb[1][ql];
            float px1 = s_pb[2][ql], py1 = s_pb[3][ql];
            float logit = logits[((size_t)b * NQ + q) * NC + lab];
            float prob  = expf(logit - s_rm[ql]) / s_rs[ql];

            float cost_bbox = fabsf(px0 - tbx0) + fabsf(py0 - tby0) +
                              fabsf(px1 - tbx1) + fabsf(py1 - tby1);
            float area_p = (px1 - px0) * (py1 - py0);
            float iw = fminf(px1, tbx1) - fmaxf(px0, tbx0);
            float ih = fminf(py1, tby1) - fmaxf(py0, tby0);
            float inter = fmaxf(iw, 0.f) * fmaxf(ih, 0.f);
            float uni = area_p + area_t - inter;
            float iou = inter / uni;
            float ew = fmaxf(px1, tbx1) - fminf(px0, tbx0);
            float eh = fmaxf(py1, tby1) - fminf(py0, tby0);
            float enc = fmaxf(ew, 0.f) * fmaxf(eh, 0.f);
            float giou = iou - (enc - uni) / enc;
            float ccut = fabsf(s_pc[ql] - tcv);

            cost = W_BBOX * cost_bbox - W_CLASS * prob
                 - W_GIOU * giou + W_CUTIN * ccut;
            out[((size_t)b * NQ + q) * NT + t] = cost;
        }
        tile[ql][tx] = cost;
    }
    __syncthreads();

    int q = q0 + tx;
#pragma unroll
    for (int r = 0; r < 4; r++) {
        int tl = ty + 8 * r;
        int t2 = t0 + tl;
        if (t2 < NT && q < NQ)
            g_CT[((size_t)b * NT + t2) * NQ + q] = tile[tx][tl];
    }
}

// ---------------------------------------------------------------------------
// Kernel 3: lazy-potential Jonker-Volgenant (lapjv-style), exact fp64.
// One CTA per batch, 256 threads, each owning 4 contiguous columns.
// v[], d[], used kept in REGISTERS; only p/way/u in smem.
// ---------------------------------------------------------------------------
__global__ void __launch_bounds__(256, 1)
lsa_kernel(float* __restrict__ outq, float* __restrict__ outt) {
    const int b = blockIdx.x;
    const int tid = threadIdx.x;
    const int lane = tid & 31;
    const int warp = tid >> 5;

    __shared__ double u[NT + 1];
    __shared__ int p[NQ + 1];
    __shared__ int way_s[NQ + 1];
    __shared__ double w_val[8];
    __shared__ int w_idx[8];
    __shared__ int s_j0;
    __shared__ int s_row;
    __shared__ double s_delta;
    __shared__ double s_k;

    double v[4], dloc[4];
    unsigned usedm = 0;
    const int base = tid * 4 + 1;         // first owned column, 1-indexed
    const bool owner = (base <= NQ);      // threads 0..224 own 4 cols each

#pragma unroll
    for (int c = 0; c < 4; c++) v[c] = 0.0;
    for (int j = tid; j <= NQ; j += 256) p[j] = 0;
    for (int j = tid; j <= NT; j += 256) u[j] = 0.0;
    __syncthreads();

    const float* __restrict__ Cb = g_CT + (size_t)b * NT * NQ;

    for (int i = 1; i <= NT; i++) {
#pragma unroll
        for (int c = 0; c < 4; c++) dloc[c] = DBL_MAX;
        usedm = 0;
        if (tid == 0) { p[0] = i; s_j0 = 0; s_delta = 0.0; }
        __syncthreads();

        while (true) {
            if (tid == 0) {
                int i0 = p[s_j0];
                s_row = i0 - 1;
                s_k = s_delta - u[i0];
            }
            __syncthreads();
            const int j0 = s_j0;
            const double k = s_k;
            const float* crow = Cb + (size_t)s_row * NQ;

            int rel = j0 - base;
            if (rel >= 0 && rel < 4) usedm |= 1u << rel;

            double bv = DBL_MAX;
            int    bj = 0x7fffffff;
            if (owner) {
                float4 cf = *reinterpret_cast<const float4*>(crow + (base - 1));
                float cs[4] = {cf.x, cf.y, cf.z, cf.w};
#pragma unroll
                for (int c = 0; c < 4; c++) {
                    if (!((usedm >> c) & 1u)) {
                        double alt = k + (double)cs[c] - v[c];
                        if (alt < dloc[c]) { dloc[c] = alt; way_s[base + c] = j0; }
                        if (dloc[c] < bv) { bv = dloc[c]; bj = base + c; }
                    }
                }
            }
#pragma unroll
            for (int o = 16; o; o >>= 1) {
                double ov = __shfl_down_sync(0xffffffffu, bv, o);
                int    oj = __shfl_down_sync(0xffffffffu, bj, o);
                if (ov < bv || (ov == bv && oj < bj)) { bv = ov; bj = oj; }
            }
            if (lane == 0) { w_val[warp] = bv; w_idx[warp] = bj; }
            __syncthreads();
            if (tid == 0) {
                double bb = w_val[0]; int jj = w_idx[0];
#pragma unroll
                for (int w = 1; w < 8; w++) {
                    double ov = w_val[w]; int oj = w_idx[w];
                    if (ov < bb || (ov == bb && oj < jj)) { bb = ov; jj = oj; }
                }
                s_delta = bb; s_j0 = jj;
            }
            __syncthreads();
            if (p[s_j0] == 0) break;
        }

        const int    jfree = s_j0;
        const double dstar = s_delta;
        if (owner) {
#pragma unroll
            for (int c = 0; c < 4; c++) {
                if ((usedm >> c) & 1u) {
                    v[c] += dloc[c] - dstar;
                    u[p[base + c]] += dstar - dloc[c];
                }
            }
        }
        if (tid == 0) u[i] += dstar;
        __syncthreads();
        if (tid == 0) {
            int j0 = jfree;
            while (j0) { int j1 = way_s[j0]; p[j0] = p[j1]; j0 = j1; }
        }
        __syncthreads();
    }

    for (int j = tid + 1; j <= NQ; j += 256) {
        int r = p[j];
        if (r > 0) outq[b * NT + (r - 1)] = (float)(j - 1);
    }
    for (int t = tid; t < NT; t += 256) outt[b * NT + t] = (float)t;
}

// ---------------------------------------------------------------------------
extern "C" void kernel_launch(void* const* d_in, const int* in_sizes, int n_in,
                              void* d_out, int out_size) {
    const float* logits = (const float*)d_in[0];
    const float* pboxes = (const float*)d_in[1];
    const float* pcut   = (const float*)d_in[2];
    const int*   tlab   = (const int*)d_in[3];
    const float* tboxes = (const float*)d_in[4];
    const float* tcut   = (const float*)d_in[5];
    float* out = (float*)d_out;

    int rows = NB * NQ;
    int threads = 256;
    int blocks = (rows * 32 + threads - 1) / threads;
    softmax_stats_kernel<<<blocks, threads>>>(logits);

    dim3 cgrid((NT + 31) / 32, (NQ + 31) / 32, NB);
    cost_fused_kernel<<<cgrid, dim3(32, 8)>>>(logits, pboxes, pcut, tlab,
                                              tboxes, tcut, out);

    float* outq = out + (size_t)NB * NQ * NT;
    float* outt = outq + (size_t)NB * NT;
    lsa_kernel<<<NB, 256>>>(outq, outt);
}

// round 4
// speedup vs baseline: 2.5298x; 2.2255x over previous
#include <cuda_runtime.h>
#include <math.h>
#include <float.h>

#define NB 32
#define NQ 900
#define NT 300
#define NC 256

#define W_CLASS 1.0f
#define W_BBOX  5.0f
#define W_GIOU  2.0f
#define W_CUTIN 2.0f

#define SCALE_F 17179869184.0f      // 2^34
#define PBIAS   (1ULL << 62)

// Scratch (allocation-free rule: __device__ globals)
__device__ float g_CT[(size_t)NB * NT * NQ];          // transposed cost [b][t][q]
__device__ float g_rmax[NB * NQ];
__device__ float g_rsum[NB * NQ];
__device__ unsigned long long g_rowmin[NB * NT];      // packed (fix<<11|col)+bias

__device__ __forceinline__ long long f2fix(float x) {
    return __float2ll_rn(x * SCALE_F);                // exact: 2^34 is a power of 2
}

// ---------------------------------------------------------------------------
// Kernel 1: softmax stats (max, sumexp) per (b,q). 1 warp/row.
// Also re-initializes g_rowmin every launch (graph replay safety).
// ---------------------------------------------------------------------------
__global__ void softmax_stats_kernel(const float* __restrict__ logits) {
    int gtid = blockIdx.x * blockDim.x + threadIdx.x;
    if (gtid < NB * NT) g_rowmin[gtid] = ~0ULL;

    int warp = gtid >> 5;
    int lane = threadIdx.x & 31;
    if (warp >= NB * NQ) return;
    const float* row = logits + (size_t)warp * NC;
    float vals[NC / 32];
    float m = -INFINITY;
#pragma unroll
    for (int k = 0; k < NC / 32; k++) {
        vals[k] = row[lane + 32 * k];
        m = fmaxf(m, vals[k]);
    }
#pragma unroll
    for (int o = 16; o; o >>= 1) m = fmaxf(m, __shfl_xor_sync(0xffffffffu, m, o));
    float s = 0.f;
#pragma unroll
    for (int k = 0; k < NC / 32; k++) s += expf(vals[k] - m);
#pragma unroll
    for (int o = 16; o; o >>= 1) s += __shfl_xor_sync(0xffffffffu, s, o);
    if (lane == 0) { g_rmax[warp] = m; g_rsum[warp] = s; }
}

// ---------------------------------------------------------------------------
// Kernel 2 (fused): cost matrix in BOTH layouts + per-(b,t) packed row minima.
// Block (32,8): x = t in tile, y strides 4 q rows. 32x32 tile transpose.
// ---------------------------------------------------------------------------
__global__ void __launch_bounds__(256)
cost_fused_kernel(const float* __restrict__ logits,
                  const float* __restrict__ pboxes,
                  const float* __restrict__ pcut,
                  const int*   __restrict__ tlab,
                  const float* __restrict__ tboxes,
                  const float* __restrict__ tcut,
                  float* __restrict__ out) {
    int b = blockIdx.z;
    int t0 = blockIdx.x << 5;
    int q0 = blockIdx.y << 5;

    __shared__ float s_tb[4][32];
    __shared__ int   s_lab[32];
    __shared__ float s_tc[32];
    __shared__ float s_pb[4][32];
    __shared__ float s_pc[32], s_rm[32], s_rs[32];
    __shared__ float tile[32][33];
    __shared__ unsigned long long srow[32];

    int tx = threadIdx.x, ty = threadIdx.y;
    int tid = ty * 32 + tx;

    if (ty == 0) srow[tx] = ~0ULL;
    if (tid < 32) {
        int t = t0 + tid;
        if (t < NT) {
            const float* tb = tboxes + (((size_t)b * NT + t) << 2);
            s_tb[0][tid] = tb[0]; s_tb[1][tid] = tb[1];
            s_tb[2][tid] = tb[2]; s_tb[3][tid] = tb[3];
            s_lab[tid] = tlab[b * NT + t];
            s_tc[tid]  = tcut[b * NT + t];
        }
    } else if (tid < 64) {
        int l = tid - 32; int q = q0 + l;
        if (q < NQ) {
            const float* pb = pboxes + (((size_t)b * NQ + q) << 2);
            s_pb[0][l] = pb[0]; s_pb[1][l] = pb[1];
            s_pb[2][l] = pb[2]; s_pb[3][l] = pb[3];
        }
    } else if (tid < 96) {
        int l = tid - 64; int q = q0 + l;
        if (q < NQ) {
            s_pc[l] = pcut[b * NQ + q];
            s_rm[l] = g_rmax[b * NQ + q];
            s_rs[l] = g_rsum[b * NQ + q];
        }
    }
    __syncthreads();

    int t = t0 + tx;
    bool tvalid = t < NT;
    float tbx0 = s_tb[0][tx], tby0 = s_tb[1][tx];
    float tbx1 = s_tb[2][tx], tby1 = s_tb[3][tx];
    int   lab  = tvalid ? s_lab[tx] : 0;
    float tcv  = s_tc[tx];
    float area_t = (tbx1 - tbx0) * (tby1 - tby0);

    unsigned long long lmin = ~0ULL;

#pragma unroll
    for (int r = 0; r < 4; r++) {
        int ql = ty + 8 * r;
        int q  = q0 + ql;
        float cost = 0.f;
        if (tvalid && q < NQ) {
            float px0 = s_pb[0][ql], py0 = s_pb[1][ql];
            float px1 = s_pb[2][ql], py1 = s_pb[3][ql];
            float logit = logits[((size_t)b * NQ + q) * NC + lab];
            float prob  = expf(logit - s_rm[ql]) / s_rs[ql];

            float cost_bbox = fabsf(px0 - tbx0) + fabsf(py0 - tby0) +
                              fabsf(px1 - tbx1) + fabsf(py1 - tby1);
            float area_p = (px1 - px0) * (py1 - py0);
            float iw = fminf(px1, tbx1) - fmaxf(px0, tbx0);
            float ih = fminf(py1, tby1) - fmaxf(py0, tby0);
            float inter = fmaxf(iw, 0.f) * fmaxf(ih, 0.f);
            float uni = area_p + area_t - inter;
            float iou = inter / uni;
            float ew = fmaxf(px1, tbx1) - fminf(px0, tbx0);
            float eh = fmaxf(py1, tby1) - fminf(py0, tby0);
            float enc = fmaxf(ew, 0.f) * fmaxf(eh, 0.f);
            float giou = iou - (enc - uni) / enc;
            float ccut = fabsf(s_pc[ql] - tcv);

            cost = W_BBOX * cost_bbox - W_CLASS * prob
                 - W_GIOU * giou + W_CUTIN * ccut;
            out[((size_t)b * NQ + q) * NT + t] = cost;

            unsigned long long pk =
                (unsigned long long)(f2fix(cost) * 2048LL + (long long)(q + 1)) + PBIAS;
            if (pk < lmin) lmin = pk;
        }
        tile[ql][tx] = cost;
    }
    if (lmin != ~0ULL) atomicMin(&srow[tx], lmin);
    __syncthreads();

    int q = q0 + tx;
#pragma unroll
    for (int r = 0; r < 4; r++) {
        int tl = ty + 8 * r;
        int t2 = t0 + tl;
        if (t2 < NT && q < NQ)
            g_CT[((size_t)b * NT + t2) * NQ + q] = tile[tx][tl];
    }
    if (ty == 0 && tvalid) atomicMin(&g_rowmin[b * NT + t], srow[tx]);
}

// ---------------------------------------------------------------------------
// Kernel 3: JV with greedy row-reduction init + int64 fixed-point Dijkstra.
// One CTA per batch, 256 threads, 4 contiguous columns per thread (regs).
// One barrier per Dijkstra iteration (triple-buffered packed-min slots).
// ---------------------------------------------------------------------------
__global__ void __launch_bounds__(256, 1)
lsa_kernel(float* __restrict__ outq, float* __restrict__ outt) {
    const int b = blockIdx.x;
    const int tid = threadIdx.x;
    const int warp = tid >> 5;
    const int lane = tid & 31;

    __shared__ long long u_s[NT + 1];
    __shared__ int p_s[NQ + 1];
    __shared__ int way_s[NQ + 1];
    __shared__ unsigned long long red[3][8];
    __shared__ int freelist[NT];
    __shared__ int amin[NT + 1];
    __shared__ int s_nf;

    long long v[4], d[4];
    const int base = tid * 4 + 1;
    const bool owner = base <= NQ;
    const long long INF = 1LL << 60;

#pragma unroll
    for (int c = 0; c < 4; c++) v[c] = 0;
    for (int j = tid; j <= NQ; j += 256) p_s[j] = 0;
    for (int i = tid; i < NT; i += 256) {
        long long pk = (long long)(g_rowmin[b * NT + i] - PBIAS);
        u_s[i + 1] = pk >> 11;
        amin[i + 1] = (int)(pk & 2047);
    }
    if (tid < 24) red[tid >> 3][tid & 7] = ~0ULL;
    if (tid == 0) u_s[0] = 0;
    __syncthreads();

    // Greedy assignment of each row to its argmin column (serial, trivial).
    if (tid == 0) {
        int nf = 0;
        for (int i = 1; i <= NT; i++) {
            int j = amin[i];
            if (p_s[j] == 0) p_s[j] = i;
            else freelist[nf++] = i;
        }
        s_nf = nf;
    }
    __syncthreads();
    const int nf = s_nf;
    const float* __restrict__ Cb = g_CT + (size_t)b * NT * NQ;
    int par = 0;

    for (int fi = 0; fi < nf; fi++) {
#pragma unroll
        for (int c = 0; c < 4; c++) d[c] = INF;
        unsigned usedm = 0;
        if (tid == 0) p_s[0] = freelist[fi];
        __syncthreads();

        int j0 = 0;
        long long delta = 0;
        while (true) {
            int row = p_s[j0];
            long long k = delta - u_s[row];

            int rel = j0 - base;
            if (rel >= 0 && rel < 4) usedm |= 1u << rel;

            unsigned long long lmin = ~0ULL;
            if (owner) {
                float4 cf = *reinterpret_cast<const float4*>(
                    Cb + (size_t)(row - 1) * NQ + (base - 1));
                long long ci0 = f2fix(cf.x), ci1 = f2fix(cf.y);
                long long ci2 = f2fix(cf.z), ci3 = f2fix(cf.w);
                long long ci[4] = {ci0, ci1, ci2, ci3};
#pragma unroll
                for (int c = 0; c < 4; c++) {
                    if (!((usedm >> c) & 1u)) {
                        long long alt = k + ci[c] - v[c];
                        if (alt < d[c]) { d[c] = alt; way_s[base + c] = j0; }
                        unsigned long long pk =
                            (unsigned long long)(d[c] * 2048LL + (long long)(base + c)) + PBIAS;
                        if (pk < lmin) lmin = pk;
                    }
                }
            }
            int nxt = par + 1; if (nxt == 3) nxt = 0;
            if (lane == 0) red[nxt][warp] = ~0ULL;   // safe: last read 2 bars ago
            if (lmin != ~0ULL) atomicMin(&red[par][warp], lmin);
            __syncthreads();

            unsigned long long m = red[par][0];
#pragma unroll
            for (int w = 1; w < 8; w++) {
                unsigned long long x = red[par][w];
                if (x < m) m = x;
            }
            par = nxt;
            long long pks = (long long)(m - PBIAS);
            delta = pks >> 11;
            j0 = (int)(pks & 2047);
            if (p_s[j0] == 0) break;
        }

        // Telescoped dual updates (distinct rows per used column: no conflicts)
        const long long dstar = delta;
        if (owner) {
#pragma unroll
            for (int c = 0; c < 4; c++) {
                if ((usedm >> c) & 1u) {
                    v[c] += d[c] - dstar;
                    u_s[p_s[base + c]] += dstar - d[c];
                }
            }
        }
        if (tid == 0) u_s[p_s[0]] += dstar;
        __syncthreads();
        if (tid == 0) {
            int jj = j0;
            while (jj) { int j1 = way_s[jj]; p_s[jj] = p_s[j1]; jj = j1; }
        }
        // next iteration's setup barrier orders the augment before use of p_s
    }
    __syncthreads();

    for (int j = tid + 1; j <= NQ; j += 256) {
        int r = p_s[j];
        if (r > 0) outq[b * NT + (r - 1)] = (float)(j - 1);
    }
    for (int t = tid; t < NT; t += 256) outt[b * NT + t] = (float)t;
}

// ---------------------------------------------------------------------------
extern "C" void kernel_launch(void* const* d_in, const int* in_sizes, int n_in,
                              void* d_out, int out_size) {
    const float* logits = (const float*)d_in[0];
    const float* pboxes = (const float*)d_in[1];
    const float* pcut   = (const float*)d_in[2];
    const int*   tlab   = (const int*)d_in[3];
    const float* tboxes = (const float*)d_in[4];
    const float* tcut   = (const float*)d_in[5];
    float* out = (float*)d_out;

    int rows = NB * NQ;
    int threads = 256;
    int blocks = (rows * 32 + threads - 1) / threads;
    softmax_stats_kernel<<<blocks, threads>>>(logits);

    dim3 cgrid((NT + 31) / 32, (NQ + 31) / 32, NB);
    cost_fused_kernel<<<cgrid, dim3(32, 8)>>>(logits, pboxes, pcut, tlab,
                                              tboxes, tcut, out);

    float* outq = out + (size_t)NB * NQ * NT;
    float* outt = outq + (size_t)NB * NT;
    lsa_kernel<<<NB, 256>>>(outq, outt);
}